// round 12
// baseline (speedup 1.0000x reference)
#include <cuda_runtime.h>
#include <cuda_bf16.h>
#include <math.h>
#include <cstdint>

// ---------------- problem constants ----------------
#define BATCH 64
#define TSTEPS 20
#define CIN 25
#define HID 64
#define SP 25
#define NPIX 625
#define GATES 256
#define POOLD 12
#define FEAT 9216
#define FC1N 128
#define FC2N 64

#define PW 27                 // padded plane width (25 + border)
#define PPLANE 729            // 27*27

#define K0TOT ((CIN + HID) * 9)   // 801
#define K0PAD 832                 // 26 stages of 32
#define K1TOT (2 * HID * 9)       // 1152
#define K1PAD 1152                // 36 stages
#define KCTOT (HID * 9)           // 576
#define KCPAD 576                 // 18 stages
#define TAPSZ 9216                // 1152 * sizeof(int2)

// ---------------- scratch (device globals, no allocation) ----------------
// activations packed u32 = (bf16 hi) | (bf16 lo << 16)? NO: hi<<16 | lo (as before)
__device__ __align__(16) uint32_t g_xn[(long)TSTEPS * BATCH * (CIN + 1) * PPLANE];
__device__ __align__(16) uint32_t g_h0a[(long)BATCH * (HID + 1) * PPLANE];
__device__ __align__(16) uint32_t g_h0b[(long)BATCH * (HID + 1) * PPLANE];
__device__ __align__(16) uint32_t g_h1a[(long)BATCH * (HID + 1) * PPLANE];
__device__ __align__(16) uint32_t g_h1b[(long)BATCH * (HID + 1) * PPLANE];
__device__ __align__(16) float g_c0[(long)BATCH * NPIX * HID];
__device__ __align__(16) float g_c1[(long)BATCH * NPIX * HID];
__device__ __align__(16) float g_y [(long)BATCH * HID * NPIX];
__device__ __align__(16) float g_pool[(long)BATCH * FEAT];
__device__ float g_f1[BATCH * FC1N];
__device__ float g_f2[BATCH * FC2N];
__device__ float g_f3[BATCH * 2];
// weights in MMA-fragment order, u32 = packed bf16 k-pair (low = even k)
__device__ __align__(16) uint32_t g_w0f[GATES * K0PAD];
__device__ __align__(16) uint32_t g_w1f[GATES * K1PAD];
__device__ __align__(16) uint32_t g_wcf[HID * KCPAD];
__device__ __align__(16) int2 g_tap0[K0PAD];
__device__ __align__(16) int2 g_tap1[K1PAD];
__device__ __align__(16) int2 g_tapc[KCPAD];

// ---------------- helpers ----------------
__device__ __forceinline__ uint32_t smem_u32(const void* p) {
    uint32_t a;
    asm("{ .reg .u64 t; cvta.to.shared.u64 t, %1; cvt.u32.u64 %0, t; }" : "=r"(a) : "l"(p));
    return a;
}
#define LDSM4(r, a) \
    asm volatile("ldmatrix.sync.aligned.m8n8.x4.shared.b16 {%0,%1,%2,%3}, [%4];" \
        : "=r"((r)[0]), "=r"((r)[1]), "=r"((r)[2]), "=r"((r)[3]) : "r"(a))

__device__ __forceinline__ void mma_bf16(float* c, const uint32_t* a, const uint32_t* b) {
    asm volatile(
        "mma.sync.aligned.m16n8k16.row.col.f32.bf16.bf16.f32 "
        "{%0,%1,%2,%3}, {%4,%5,%6,%7}, {%8,%9}, {%0,%1,%2,%3};"
        : "+f"(c[0]), "+f"(c[1]), "+f"(c[2]), "+f"(c[3])
        : "r"(a[0]), "r"(a[1]), "r"(a[2]), "r"(a[3]), "r"(b[0]), "r"(b[1]));
}

__device__ __forceinline__ float sigm(float x) { return 1.f / (1.f + __expf(-x)); }
__device__ __forceinline__ float tanh_acc(float x) {
    float e = __expf(-2.f * fabsf(x));
    float t = (1.f - e) / (1.f + e);
    return copysignf(t, x);
}
__device__ __forceinline__ uint32_t pack_hl(float v) {
    __nv_bfloat16 h = __float2bfloat16(v);
    float hf = __bfloat162float(h);
    __nv_bfloat16 lo = __float2bfloat16(v - hf);
    return ((uint32_t)__bfloat16_as_ushort(h) << 16) | (uint32_t)__bfloat16_as_ushort(lo);
}
__device__ __forceinline__ int swz(int row, int kbyte) {
    return row * 64 + (kbyte ^ (((row >> 1) & 3) << 4));
}

// ---------------- zero all recurrent/padded state ----------------
#define NXZ ((long)TSTEPS * BATCH * (CIN + 1) * PPLANE)
#define NHZ ((long)BATCH * (HID + 1) * PPLANE)
#define NCZ ((long)BATCH * NPIX * HID)
__global__ void zero_all_kernel(uint32_t* xn, uint32_t* h0a, uint32_t* h0b,
                                uint32_t* h1a, uint32_t* h1b, float* c0, float* c1) {
    long i = (long)blockIdx.x * blockDim.x + threadIdx.x;
    if (i < NXZ) xn[i] = 0u;
    if (i < NHZ) { h0a[i] = 0u; h0b[i] = 0u; h1a[i] = 0u; h1b[i] = 0u; }
    if (i < NCZ) { c0[i] = 0.f; c1[i] = 0.f; }
}

// ---------------- LayerNorm -> padded planes ----------------
__global__ void ln_kernel(const float* __restrict__ x,
                          const float* __restrict__ gamma,
                          const float* __restrict__ beta,
                          uint32_t* __restrict__ xn) {
    int idx = blockIdx.x * blockDim.x + threadIdx.x;
    if (idx >= BATCH * TSTEPS * NPIX) return;
    int p = idx % NPIX;
    int t = (idx / NPIX) % TSTEPS;
    int b = idx / (NPIX * TSTEPS);
    const float* base = x + ((long)(b * TSTEPS + t) * CIN) * NPIX + p;
    float v[CIN];
    float s = 0.f;
    #pragma unroll
    for (int c = 0; c < CIN; c++) { v[c] = base[c * NPIX]; s += v[c]; }
    float mu = s * (1.f / CIN);
    float q = 0.f;
    #pragma unroll
    for (int c = 0; c < CIN; c++) { float d = v[c] - mu; q += d * d; }
    float rs = rsqrtf(q * (1.f / CIN) + 1e-5f);
    int py = p / SP, px = p - py * SP;
    uint32_t* ob = xn + ((long)(t * BATCH + b) * (CIN + 1)) * PPLANE
                      + (py + 1) * PW + px + 1;
    #pragma unroll
    for (int c = 0; c < CIN; c++) ob[c * PPLANE] = pack_hl((v[c] - mu) * rs * gamma[c] + beta[c]);
}

// ---------------- merged prep: fragment-ordered weights + tap tables ----------------
// Fragment u32 layout: i = (((s*TOTW + wnG)*32 + l)*2 + h)*16? NO — bit layout:
//   bit0 = reg r, bits1-2 = nf, bit3 = plane, bit4 = half h, bits5-9 = lane l,
//   bits10.. = wnG (twbits), rest = stage s.
// Value = W[n][k..k+1] packed, n from (wnG, nf, l>>2) with optional LSTM perm,
//   k = s*32 + h*16 + r*8 + (l&3)*2.
__device__ __forceinline__ void wfrag(const float* __restrict__ W, uint32_t* __restrict__ out,
                                      int i, int Ktot, int twbits, int perm) {
    int r = i & 1;
    int nf = (i >> 1) & 3;
    int plane = (i >> 3) & 1;
    int h = (i >> 4) & 1;
    int l = (i >> 5) & 31;
    int wnG = (i >> 10) & ((1 << twbits) - 1);
    int s = i >> (10 + twbits);
    int n;
    if (perm) n = nf * 64 + (wnG >> 2) * 32 + (wnG & 3) * 8 + (l >> 2);
    else      n = wnG * 32 + nf * 8 + (l >> 2);
    int k = s * 32 + h * 16 + r * 8 + (l & 3) * 2;
    float v0 = (k < Ktot) ? W[(long)n * Ktot + k] : 0.f;
    float v1 = (k + 1 < Ktot) ? W[(long)n * Ktot + k + 1] : 0.f;
    __nv_bfloat16 b0 = __float2bfloat16(v0);
    __nv_bfloat16 b1 = __float2bfloat16(v1);
    uint32_t pv;
    if (plane == 0) {
        pv = (uint32_t)__bfloat16_as_ushort(b0) | ((uint32_t)__bfloat16_as_ushort(b1) << 16);
    } else {
        __nv_bfloat16 l0 = __float2bfloat16(v0 - __bfloat162float(b0));
        __nv_bfloat16 l1 = __float2bfloat16(v1 - __bfloat162float(b1));
        pv = (uint32_t)__bfloat16_as_ushort(l0) | ((uint32_t)__bfloat16_as_ushort(l1) << 16);
    }
    out[i] = pv;
}
__device__ __forceinline__ int2 tap_make(int j, int Ktot, int C0) {
    if (j >= Ktot) return make_int2(C0 * PPLANE, 0);
    int cc = j / 9, r = j - cc * 9;
    int ky = r / 3 - 1, kx = r - (r / 3) * 3 - 1;
    int sel = cc >= C0;
    int c = sel ? cc - C0 : cc;
    return make_int2(c * PPLANE + ky * PW + kx, sel);
}
__global__ void prep_kernel(const float* w0, const float* w1, const float* wc) {
    const int S0 = GATES * K0PAD, S1 = GATES * K1PAD, S2 = HID * KCPAD;
    int i = blockIdx.x * blockDim.x + threadIdx.x;
    if (i < S0) { wfrag(w0, g_w0f, i, K0TOT, 3, 1); return; }
    i -= S0;
    if (i < S1) { wfrag(w1, g_w1f, i, K1TOT, 3, 1); return; }
    i -= S1;
    if (i < S2) { wfrag(wc, g_wcf, i, KCTOT, 1, 0); return; }
    i -= S2;
    if (i < K0PAD) { g_tap0[i] = tap_make(i, K0TOT, CIN); return; }
    i -= K0PAD;
    if (i < K1PAD) { g_tap1[i] = tap_make(i, K1TOT, HID); return; }
    i -= K1PAD;
    if (i < KCPAD) { g_tapc[i] = tap_make(i, KCTOT, HID); return; }
}

// ---------------- pipelined mma.sync implicit-GEMM conv (+fused epilogue) ----------------
// CTA: M=128 pixels x NCH=NWN*32 channels; warps (2 M) x (NWN N); warp tile 64x32.
// A: branch-free gather -> smem (hi/lo planes) -> LDSM. B: DIRECT from gmem in
// fragment order (8x LDG.128/thread/stage), no smem, no cp.async.
// EPI=0 (NWN=4, 256 thr, 2 CTAs/SM, blockIdx.z = nblk): fused LSTM gates for 32
//   hidden units, h padded-plane out, c pixel-major in/out via smem staging.
// EPI=1 (NWN=2, 128 thr): bias+relu, fp32 unpadded plane-major out.
template<int NWN, int EPI>
__global__ __launch_bounds__(NWN * 64, 2)
void convmma_kernel(const uint32_t* __restrict__ in0, int C0,
                    const uint32_t* __restrict__ in1, int C1,
                    const int2* __restrict__ tap,
                    const uint32_t* __restrict__ Bf,
                    int Kpad,
                    const float* __restrict__ bias,
                    void* __restrict__ out_h_, float* __restrict__ out_c) {
    constexpr int NTH = NWN * 64;
    constexpr int TOTW = (EPI == 0) ? 2 * NWN : NWN;
    constexpr int APLANE = 128 * 64;        // one bf16 plane: 128 rows x 32 k x 2B
    constexpr int BUF = 2 * APLANE;
    constexpr int AE = 4096 / NTH;          // packed A elems per thread per stage

    extern __shared__ char smem[];
    const uint32_t sb = smem_u32(smem);
    int2* tapS = (int2*)(smem + 2 * BUF);
    float* cs = (float*)(smem + 2 * BUF + TAPSZ);                       // [128][36]
    uint32_t* hs = (uint32_t*)(smem + 2 * BUF + TAPSZ + 128 * 36 * 4);  // [128][33]

    const int tid = threadIdx.x;
    const int l = tid & 31;
    const int wid = tid >> 5;
    const int wm = wid & 1;
    const int wn = wid >> 1;
    const int img = blockIdx.y;
    const int pix0 = blockIdx.x * 128;
    const int nblk = (EPI == 0) ? blockIdx.z : 0;
    const int nbw = (EPI == 0) ? (nblk * NWN + wn) : wn;

    const int arow = tid & 127;
    const int ap = pix0 + arow;
    const int apc = ap < NPIX ? ap : NPIX - 1;
    const int apy = apc / SP;
    const int apx = apc - apy * SP;
    const int papd = (apy + 1) * PW + apx + 1;
    const int kbase = tid >> 7;             // 0..(NTH/128 - 1)

    const uint32_t* in0i = in0 + (long)img * (C0 + 1) * PPLANE;
    const uint32_t* in1i = in1 + (long)img * (C1 + 1) * PPLANE;
    // per-thread fragment base (u32 index): advances by TOTW*1024 per stage
    const uint32_t* bfp = Bf + ((long)nbw * 32 + l) * 32;

    const int nstage = Kpad >> 5;

    uint32_t ar[AE];

    auto ldgA = [&](int s) {
        const int k0 = s << 5;
        #pragma unroll
        for (int e = 0; e < AE; e++) {
            int k = kbase * AE + e;
            int2 t = tapS[k0 + k];
            const uint32_t* base = t.y ? in1i : in0i;
            ar[e] = __ldg(base + t.x + papd);
        }
    };
    auto stsA = [&](int s) {
        char* buf = smem + (s & 1) * BUF;
        #pragma unroll
        for (int e = 0; e < AE; e += 2) {
            int k = kbase * AE + e;
            int off = swz(arow, k * 2);
            uint32_t hi2 = (ar[e] >> 16) | (ar[e + 1] & 0xffff0000u);
            uint32_t lo2 = (ar[e] & 0xffffu) | (ar[e + 1] << 16);
            *(uint32_t*)(buf + off) = hi2;
            *(uint32_t*)(buf + APLANE + off) = lo2;
        }
    };

    float acc[4][4][4];
    #pragma unroll
    for (int a = 0; a < 4; a++)
        #pragma unroll
        for (int b = 0; b < 4; b++)
            #pragma unroll
            for (int c = 0; c < 4; c++) acc[a][b][c] = 0.f;

    // ---- prologue ----
    for (int i = tid; i < Kpad; i += NTH) tapS[i] = tap[i];
    if (EPI == 0) {
        #pragma unroll
        for (int i = 0; i < 1024 / NTH; i++) {
            int idx4 = tid + i * NTH;
            int p = idx4 >> 3, jq = idx4 & 7;
            int pg = pix0 + p;
            float4 v = make_float4(0.f, 0.f, 0.f, 0.f);
            if (pg < NPIX)
                v = *(const float4*)(out_c + ((long)img * NPIX + pg) * 64 + nblk * 32 + jq * 4);
            *(float4*)(cs + p * 36 + jq * 4) = v;
        }
    }
    __syncthreads();          // taps visible
    ldgA(0);
    stsA(0);
    ldgA(1);
    __syncthreads();

    for (int s = 0; s < nstage; s++) {
        const uint32_t cur = sb + (s & 1) * BUF;
        const uint32_t sAh = cur, sAl = cur + APLANE;
        const uint32_t* bstage = bfp + (long)s * TOTW * 1024;

        #pragma unroll
        for (int h = 0; h < 2; h++) {
            // B fragments: 16 u32 = [plane(2)][nf(4)][reg(2)] for this half
            uint32_t br[16];
            {
                const uint4* bp = (const uint4*)(bstage + h * 16);
                *(uint4*)&br[0]  = __ldg(bp + 0);
                *(uint4*)&br[4]  = __ldg(bp + 1);
                *(uint4*)&br[8]  = __ldg(bp + 2);
                *(uint4*)&br[12] = __ldg(bp + 3);
            }
            const int aro = wm * 64 + (l & 15);
            const int ako = (h * 16 + (l >> 4) * 8) * 2;
            #pragma unroll
            for (int mf = 0; mf < 4; mf++) {
                uint32_t ah[4], al[4];
                LDSM4(ah, sAh + swz(aro + mf * 16, ako));
                LDSM4(al, sAl + swz(aro + mf * 16, ako));
                #pragma unroll
                for (int nf = 0; nf < 4; nf++) {
                    mma_bf16(acc[mf][nf], ah, &br[nf * 2]);        // a_hi * w_hi
                    mma_bf16(acc[mf][nf], ah, &br[8 + nf * 2]);    // a_hi * w_lo
                    mma_bf16(acc[mf][nf], al, &br[nf * 2]);        // a_lo * w_hi
                }
            }
        }
        if (s + 1 < nstage) stsA(s + 1);
        if (s + 2 < nstage) ldgA(s + 2);
        __syncthreads();
    }

    if (EPI == 0) {
        #pragma unroll
        for (int mf = 0; mf < 4; mf++) {
            #pragma unroll
            for (int c = 0; c < 4; c++) {
                int p = wm * 64 + mf * 16 + (l >> 2) + ((c >> 1) & 1) * 8;
                int j = wn * 8 + (l & 3) * 2 + (c & 1);
                int u = nblk * 32 + j;
                float zi = acc[mf][0][c] + __ldg(bias + u);
                float zf = acc[mf][1][c] + __ldg(bias + 64 + u);
                float zo = acc[mf][2][c] + __ldg(bias + 128 + u);
                float zg = acc[mf][3][c] + __ldg(bias + 192 + u);
                if (pix0 + p < NPIX) {
                    float ig = sigm(zi), fg = sigm(zf), og = sigm(zo);
                    float gg = tanh_acc(zg);
                    float cn = fg * cs[p * 36 + j] + ig * gg;
                    cs[p * 36 + j] = cn;
                    hs[p * 33 + j] = pack_hl(og * tanh_acc(cn));
                }
            }
        }
        __syncthreads();
        uint32_t* out_h = (uint32_t*)out_h_;
        #pragma unroll
        for (int i = 0; i < 1024 / NTH; i++) {
            int idx4 = tid + i * NTH;
            int p = idx4 >> 3, jq = idx4 & 7;
            int pg = pix0 + p;
            if (pg < NPIX)
                *(float4*)(out_c + ((long)img * NPIX + pg) * 64 + nblk * 32 + jq * 4) =
                    *(const float4*)(cs + p * 36 + jq * 4);
        }
        #pragma unroll
        for (int uu = 0; uu < 32 * 32 / NTH; uu++) {   // 32 units / CTA
            int unit = wid + (NTH / 32) * uu;
            #pragma unroll
            for (int i = 0; i < 4; i++) {
                int px = i * 32 + l;
                int pg = pix0 + px;
                if (pg < NPIX) {
                    int gy = pg / SP, gx = pg - gy * SP;
                    out_h[((long)img * (HID + 1) + nblk * 32 + unit) * PPLANE
                          + (gy + 1) * PW + gx + 1] = hs[px * 33 + unit];
                }
            }
        }
    } else {
        float* out_h = (float*)out_h_;
        #pragma unroll
        for (int mf = 0; mf < 4; mf++) {
            #pragma unroll
            for (int c = 0; c < 4; c++) {
                int p = pix0 + wm * 64 + mf * 16 + (l >> 2) + ((c >> 1) & 1) * 8;
                #pragma unroll
                for (int nf = 0; nf < 4; nf++) {
                    int n = wn * 32 + nf * 8 + (l & 3) * 2 + (c & 1);
                    float v = acc[mf][nf][c] + __ldg(bias + n);
                    if (p < NPIX)
                        out_h[((long)img * HID + n) * NPIX + p] = fmaxf(v, 0.f);
                }
            }
        }
    }
}

// ---------------- maxpool 2x2 stride 2 ----------------
__global__ void pool_kernel(const float* __restrict__ y, float* __restrict__ out) {
    int idx = blockIdx.x * blockDim.x + threadIdx.x;
    if (idx >= BATCH * HID * POOLD * POOLD) return;
    int j = idx % POOLD;
    int i = (idx / POOLD) % POOLD;
    int ch = (idx / (POOLD * POOLD)) % HID;
    int b = idx / (POOLD * POOLD * HID);
    const float* p = y + ((long)(b * HID + ch)) * NPIX + (2 * i) * SP + 2 * j;
    float m = fmaxf(fmaxf(p[0], p[1]), fmaxf(p[SP], p[SP + 1]));
    out[(long)b * FEAT + ch * (POOLD * POOLD) + i * POOLD + j] = m;
}

// ---------------- FC: one warp per output element ----------------
__global__ void fc_kernel(const float* __restrict__ in, const float* __restrict__ w,
                          const float* __restrict__ b, float* __restrict__ out,
                          int M, int N, int K, int relu) {
    int warp = (blockIdx.x * blockDim.x + threadIdx.x) >> 5;
    int lane = threadIdx.x & 31;
    if (warp >= M * N) return;
    int m = warp / N, n = warp - m * N;
    const float* ir = in + (long)m * K;
    const float* wr = w + (long)n * K;
    float s = 0.f;
    for (int k = lane; k < K; k += 32) s += ir[k] * wr[k];
    #pragma unroll
    for (int o = 16; o; o >>= 1) s += __shfl_xor_sync(0xFFFFFFFFu, s, o);
    if (lane == 0) {
        s += b[n];
        if (relu) s = fmaxf(s, 0.f);
        out[(long)m * N + n] = s;
    }
}

__global__ void lsm_kernel(const float* __restrict__ in, float* __restrict__ out) {
    int m = blockIdx.x * blockDim.x + threadIdx.x;
    if (m >= BATCH) return;
    float a = in[2 * m], b = in[2 * m + 1];
    float mx = fmaxf(a, b);
    float l = mx + logf(expf(a - mx) + expf(b - mx));
    out[2 * m] = a - l;
    out[2 * m + 1] = b - l;
}

// ---------------- launch ----------------
extern "C" void kernel_launch(void* const* d_in, const int* in_sizes, int n_in,
                              void* d_out, int out_size) {
    const float* x   = (const float*)d_in[0];
    const float* lg  = (const float*)d_in[1];
    const float* lb  = (const float*)d_in[2];
    const float* w0  = (const float*)d_in[3];
    const float* b0  = (const float*)d_in[4];
    const float* w1  = (const float*)d_in[5];
    const float* b1  = (const float*)d_in[6];
    const float* wc  = (const float*)d_in[7];
    const float* bc  = (const float*)d_in[8];
    const float* wf1 = (const float*)d_in[9];
    const float* bf1 = (const float*)d_in[10];
    const float* wf2 = (const float*)d_in[11];
    const float* bf2 = (const float*)d_in[12];
    const float* wf3 = (const float*)d_in[13];
    const float* bf3 = (const float*)d_in[14];
    float* out = (float*)d_out;

    uint32_t *xn, *h0a, *h0b, *h1a, *h1b;
    float *c0, *c1, *y, *pool, *f1, *f2, *f3;
    uint32_t *w0f, *w1f, *wcf;
    int2 *tap0, *tap1, *tapc;
    cudaGetSymbolAddress((void**)&xn,  g_xn);
    cudaGetSymbolAddress((void**)&h0a, g_h0a);
    cudaGetSymbolAddress((void**)&h0b, g_h0b);
    cudaGetSymbolAddress((void**)&h1a, g_h1a);
    cudaGetSymbolAddress((void**)&h1b, g_h1b);
    cudaGetSymbolAddress((void**)&c0,  g_c0);
    cudaGetSymbolAddress((void**)&c1,  g_c1);
    cudaGetSymbolAddress((void**)&y,   g_y);
    cudaGetSymbolAddress((void**)&pool, g_pool);
    cudaGetSymbolAddress((void**)&f1, g_f1);
    cudaGetSymbolAddress((void**)&f2, g_f2);
    cudaGetSymbolAddress((void**)&f3, g_f3);
    cudaGetSymbolAddress((void**)&w0f, g_w0f);
    cudaGetSymbolAddress((void**)&w1f, g_w1f);
    cudaGetSymbolAddress((void**)&wcf, g_wcf);
    cudaGetSymbolAddress((void**)&tap0, g_tap0);
    cudaGetSymbolAddress((void**)&tap1, g_tap1);
    cudaGetSymbolAddress((void**)&tapc, g_tapc);

    // smem: 2 A-bufs (2 planes x 8KB) + taps + staging
    const int SMEM0 = 2 * 16384 + TAPSZ + 128 * 36 * 4 + 128 * 33 * 4;  // 77312
    const int SMEM1 = 2 * 16384 + TAPSZ;                                // 41984
    cudaFuncSetAttribute(convmma_kernel<4, 0>, cudaFuncAttributeMaxDynamicSharedMemorySize, SMEM0);
    cudaFuncSetAttribute(convmma_kernel<2, 1>, cudaFuncAttributeMaxDynamicSharedMemorySize, SMEM1);

    zero_all_kernel<<<(int)((NXZ + 255) / 256), 256>>>(xn, h0a, h0b, h1a, h1b, c0, c1);

    const int nln = BATCH * TSTEPS * NPIX;
    ln_kernel<<<(nln + 255) / 256, 256>>>(x, lg, lb, xn);

    const int nprep = GATES * K0PAD + GATES * K1PAD + HID * KCPAD + K0PAD + K1PAD + KCPAD;
    prep_kernel<<<(nprep + 255) / 256, 256>>>(w0, w1, wc);

    uint32_t* h0buf[2] = {h0a, h0b};
    uint32_t* h1buf[2] = {h1a, h1b};
    dim3 grid0(5, BATCH, 2);
    for (int t = 0; t < TSTEPS; t++) {
        int r = t & 1;
        const uint32_t* xt = xn + (long)t * BATCH * (CIN + 1) * PPLANE;
        convmma_kernel<4, 0><<<grid0, 256, SMEM0>>>(
            xt, CIN, h0buf[r], HID, tap0, w0f, K0PAD, b0, h0buf[1 - r], c0);
        convmma_kernel<4, 0><<<grid0, 256, SMEM0>>>(
            h0buf[1 - r], HID, h1buf[r], HID, tap1, w1f, K1PAD, b1, h1buf[1 - r], c1);
    }
    const uint32_t* hfin = h1buf[0];   // t=19 (r=1) wrote h1buf[0]

    dim3 grid1(5, BATCH, 1);
    convmma_kernel<2, 1><<<grid1, 128, SMEM1>>>(
        hfin, HID, hfin, HID, tapc, wcf, KCPAD, bc, y, (float*)0);

    const int npool = BATCH * HID * POOLD * POOLD;
    pool_kernel<<<(npool + 255) / 256, 256>>>(y, pool);
    {
        int warps = BATCH * FC1N;
        fc_kernel<<<(warps * 32 + 255) / 256, 256>>>(pool, wf1, bf1, f1, BATCH, FC1N, FEAT, 1);
    }
    {
        int warps = BATCH * FC2N;
        fc_kernel<<<(warps * 32 + 255) / 256, 256>>>(f1, wf2, bf2, f2, BATCH, FC2N, FC1N, 1);
    }
    {
        int warps = BATCH * 2;
        fc_kernel<<<(warps * 32 + 255) / 256, 256>>>(f2, wf3, bf3, f3, BATCH, 2, FC2N, 0);
    }
    lsm_kernel<<<1, BATCH>>>(f3, out);
}

// round 13
// speedup vs baseline: 1.8011x; 1.8011x over previous
#include <cuda_runtime.h>
#include <cuda_bf16.h>
#include <math.h>
#include <cstdint>

// ---------------- problem constants ----------------
#define BATCH 64
#define TSTEPS 20
#define CIN 25
#define HID 64
#define SP 25
#define NPIX 625
#define GATES 256
#define POOLD 12
#define FEAT 9216
#define FC1N 128
#define FC2N 64

#define PW 27                 // padded plane width (25 + border)
#define PPLANE 729            // 27*27

#define K0TOT ((CIN + HID) * 9)   // 801
#define K0PAD 832                 // 26 stages of 32
#define K1TOT (2 * HID * 9)       // 1152
#define K1PAD 1152                // 36 stages
#define KCTOT (HID * 9)           // 576
#define KCPAD 576                 // 18 stages
#define TAPSZ 9216                // 1152 * sizeof(int2)

// ---------------- scratch (device globals, no allocation) ----------------
// activations packed u32 = (bf16 hi << 16) | bf16 lo, in 27x27 zero-bordered
// planes; each image has one extra always-zero plane at channel index C.
__device__ __align__(16) uint32_t g_xn[(long)TSTEPS * BATCH * (CIN + 1) * PPLANE];
__device__ __align__(16) uint32_t g_h0a[(long)BATCH * (HID + 1) * PPLANE];
__device__ __align__(16) uint32_t g_h0b[(long)BATCH * (HID + 1) * PPLANE];
__device__ __align__(16) uint32_t g_h1a[(long)BATCH * (HID + 1) * PPLANE];
__device__ __align__(16) uint32_t g_h1b[(long)BATCH * (HID + 1) * PPLANE];
__device__ __align__(16) float g_c0[(long)BATCH * NPIX * HID];
__device__ __align__(16) float g_c1[(long)BATCH * NPIX * HID];
__device__ __align__(16) float g_y [(long)BATCH * HID * NPIX];
__device__ __align__(16) float g_pool[(long)BATCH * FEAT];
__device__ float g_f1[BATCH * FC1N];
__device__ float g_f2[BATCH * FC2N];
__device__ float g_f3[BATCH * 2];
__device__ __align__(16) __nv_bfloat16 g_w0h[GATES * K0PAD];
__device__ __align__(16) __nv_bfloat16 g_w0l[GATES * K0PAD];
__device__ __align__(16) __nv_bfloat16 g_w1h[GATES * K1PAD];
__device__ __align__(16) __nv_bfloat16 g_w1l[GATES * K1PAD];
__device__ __align__(16) __nv_bfloat16 g_wch[HID * KCPAD];
__device__ __align__(16) __nv_bfloat16 g_wcl[HID * KCPAD];
__device__ __align__(16) int2 g_tap0[K0PAD];
__device__ __align__(16) int2 g_tap1[K1PAD];
__device__ __align__(16) int2 g_tapc[KCPAD];

// ---------------- helpers ----------------
__device__ __forceinline__ uint32_t smem_u32(const void* p) {
    uint32_t a;
    asm("{ .reg .u64 t; cvta.to.shared.u64 t, %1; cvt.u32.u64 %0, t; }" : "=r"(a) : "l"(p));
    return a;
}
#define LDSM4(r, a) \
    asm volatile("ldmatrix.sync.aligned.m8n8.x4.shared.b16 {%0,%1,%2,%3}, [%4];" \
        : "=r"((r)[0]), "=r"((r)[1]), "=r"((r)[2]), "=r"((r)[3]) : "r"(a))

__device__ __forceinline__ void mma_bf16(float* c, const uint32_t* a, const uint32_t* b) {
    asm volatile(
        "mma.sync.aligned.m16n8k16.row.col.f32.bf16.bf16.f32 "
        "{%0,%1,%2,%3}, {%4,%5,%6,%7}, {%8,%9}, {%0,%1,%2,%3};"
        : "+f"(c[0]), "+f"(c[1]), "+f"(c[2]), "+f"(c[3])
        : "r"(a[0]), "r"(a[1]), "r"(a[2]), "r"(a[3]), "r"(b[0]), "r"(b[1]));
}
__device__ __forceinline__ void cp_async16(uint32_t dst, const void* src) {
    asm volatile("cp.async.cg.shared.global [%0], [%1], 16;" :: "r"(dst), "l"(src));
}
#define CP_COMMIT() asm volatile("cp.async.commit_group;" ::: "memory")
#define CP_WAIT(n)  asm volatile("cp.async.wait_group %0;" :: "n"(n) : "memory")

__device__ __forceinline__ float sigm(float x) { return 1.f / (1.f + __expf(-x)); }
__device__ __forceinline__ float tanh_acc(float x) {
    float e = __expf(-2.f * fabsf(x));
    float t = (1.f - e) / (1.f + e);
    return copysignf(t, x);
}
__device__ __forceinline__ uint32_t pack_hl(float v) {
    __nv_bfloat16 h = __float2bfloat16(v);
    float hf = __bfloat162float(h);
    __nv_bfloat16 lo = __float2bfloat16(v - hf);
    return ((uint32_t)__bfloat16_as_ushort(h) << 16) | (uint32_t)__bfloat16_as_ushort(lo);
}
__device__ __forceinline__ int swz(int row, int kbyte) {
    return row * 64 + (kbyte ^ (((row >> 1) & 3) << 4));
}

// ---------------- zero all recurrent/padded state ----------------
#define NXZ ((long)TSTEPS * BATCH * (CIN + 1) * PPLANE)
#define NHZ ((long)BATCH * (HID + 1) * PPLANE)
#define NCZ ((long)BATCH * NPIX * HID)
__global__ void zero_all_kernel(uint32_t* xn, uint32_t* h0a, uint32_t* h0b,
                                uint32_t* h1a, uint32_t* h1b, float* c0, float* c1) {
    long i = (long)blockIdx.x * blockDim.x + threadIdx.x;
    if (i < NXZ) xn[i] = 0u;
    if (i < NHZ) { h0a[i] = 0u; h0b[i] = 0u; h1a[i] = 0u; h1b[i] = 0u; }
    if (i < NCZ) { c0[i] = 0.f; c1[i] = 0.f; }
}

// ---------------- LayerNorm -> padded planes ----------------
__global__ void ln_kernel(const float* __restrict__ x,
                          const float* __restrict__ gamma,
                          const float* __restrict__ beta,
                          uint32_t* __restrict__ xn) {
    int idx = blockIdx.x * blockDim.x + threadIdx.x;
    if (idx >= BATCH * TSTEPS * NPIX) return;
    int p = idx % NPIX;
    int t = (idx / NPIX) % TSTEPS;
    int b = idx / (NPIX * TSTEPS);
    const float* base = x + ((long)(b * TSTEPS + t) * CIN) * NPIX + p;
    float v[CIN];
    float s = 0.f;
    #pragma unroll
    for (int c = 0; c < CIN; c++) { v[c] = base[c * NPIX]; s += v[c]; }
    float mu = s * (1.f / CIN);
    float q = 0.f;
    #pragma unroll
    for (int c = 0; c < CIN; c++) { float d = v[c] - mu; q += d * d; }
    float rs = rsqrtf(q * (1.f / CIN) + 1e-5f);
    int py = p / SP, px = p - py * SP;
    uint32_t* ob = xn + ((long)(t * BATCH + b) * (CIN + 1)) * PPLANE
                      + (py + 1) * PW + px + 1;
    #pragma unroll
    for (int c = 0; c < CIN; c++) ob[c * PPLANE] = pack_hl((v[c] - mu) * rs * gamma[c] + beta[c]);
}

// ---------------- merged prep: weight hi/lo conversion + tap tables ----------------
// perm (LSTM, NCH=128 CTAs, nblk in bit 7): GEMM row o -> orig channel
//   gate*64 + nblk*32 + wn*8 + r, gate=(o>>3)&3, wn=(o>>5)&3, nblk=(o>>7)&1.
__device__ __forceinline__ void wconv(const float* W, __nv_bfloat16* hi, __nv_bfloat16* lo,
                                      int i, int Ktot, int Kpad, int perm) {
    int o = i / Kpad, k = i - o * Kpad;
    int orig = perm ? (((o >> 3) & 3) * 64 + ((o >> 7) & 1) * 32 + ((o >> 5) & 3) * 8 + (o & 7)) : o;
    float v = (k < Ktot) ? W[(long)orig * Ktot + k] : 0.f;
    __nv_bfloat16 h = __float2bfloat16(v);
    hi[i] = h;
    lo[i] = __float2bfloat16(v - __bfloat162float(h));
}
// tap: {plane-relative element offset, source select}; k >= Ktot -> zero plane.
__device__ __forceinline__ int2 tap_make(int j, int Ktot, int C0) {
    if (j >= Ktot) return make_int2(C0 * PPLANE, 0);
    int cc = j / 9, r = j - cc * 9;
    int ky = r / 3 - 1, kx = r - (r / 3) * 3 - 1;
    int sel = cc >= C0;
    int c = sel ? cc - C0 : cc;
    return make_int2(c * PPLANE + ky * PW + kx, sel);
}
__global__ void prep_kernel(const float* w0, const float* w1, const float* wc) {
    const int S0 = GATES * K0PAD, S1 = GATES * K1PAD, S2 = HID * KCPAD;
    int i = blockIdx.x * blockDim.x + threadIdx.x;
    if (i < S0) { wconv(w0, g_w0h, g_w0l, i, K0TOT, K0PAD, 1); return; }
    i -= S0;
    if (i < S1) { wconv(w1, g_w1h, g_w1l, i, K1TOT, K1PAD, 1); return; }
    i -= S1;
    if (i < S2) { wconv(wc, g_wch, g_wcl, i, KCTOT, KCPAD, 0); return; }
    i -= S2;
    if (i < K0PAD) { g_tap0[i] = tap_make(i, K0TOT, CIN); return; }
    i -= K0PAD;
    if (i < K1PAD) { g_tap1[i] = tap_make(i, K1TOT, HID); return; }
    i -= K1PAD;
    if (i < KCPAD) { g_tapc[i] = tap_make(i, KCTOT, HID); return; }
}

// ---------------- pipelined mma.sync implicit-GEMM conv (+fused epilogue) ----------------
// CTA: M=128 pixels x NCH=NWN*32 channels; warps (2 M) x (NWN N); warp tile 64x32.
// A gather (EPI0): thread owns (k-pair, 8 consecutive rows) — 1 LDS.128 tap-pair,
//   2 base pointers per stage, LDG[base+papd[r]], PRMT-packed STS.32 with
//   immediate offsets (swizzle XOR is compile-time per row pair).
// EPI=0 (NWN=4, 256 thr, 2 CTAs/SM, blockIdx.z = nblk): fused LSTM gates.
// EPI=1 (NWN=2, 128 thr): old-style gather, bias+relu epilogue.
template<int NWN, int EPI>
__global__ __launch_bounds__(NWN * 64, 2)
void convmma_kernel(const uint32_t* __restrict__ in0, int C0,
                    const uint32_t* __restrict__ in1, int C1,
                    const int2* __restrict__ tap,
                    const __nv_bfloat16* __restrict__ Whi,
                    const __nv_bfloat16* __restrict__ Wlo,
                    int Kpad,
                    const float* __restrict__ bias,
                    void* __restrict__ out_h_, float* __restrict__ out_c) {
    constexpr int NTH = NWN * 64;
    constexpr int NCH = NWN * 32;
    constexpr int APLANE = 128 * 64;        // one bf16 plane: 128 rows x 32 k x 2B
    constexpr int BPLANE = NCH * 64;
    constexpr int BUF = 2 * APLANE + 2 * BPLANE;
    constexpr int AE = 4096 / NTH;          // packed A elems per thread per stage

    extern __shared__ char smem[];
    const uint32_t sb = smem_u32(smem);
    int2* tapS = (int2*)(smem + 2 * BUF);
    float* cs = (float*)(smem + 2 * BUF + TAPSZ);                       // [128][36]
    uint32_t* hs = (uint32_t*)(smem + 2 * BUF + TAPSZ + 128 * 36 * 4);  // [128][33]

    const int tid = threadIdx.x;
    const int l = tid & 31;
    const int wid = tid >> 5;
    const int wm = wid & 1;
    const int wn = wid >> 1;
    const int img = blockIdx.y;
    const int pix0 = blockIdx.x * 128;
    const int nblk = (EPI == 0) ? blockIdx.z : 0;
    const int nbase = nblk * NCH;

    const uint32_t* in0i = in0 + (long)img * (C0 + 1) * PPLANE;
    const uint32_t* in1i = in1 + (long)img * (C1 + 1) * PPLANE;

    const int nstage = Kpad >> 5;

    // ---- gather geometry ----
    // EPI0: thread owns k-pair k2 = tid&15 and rows rg*8..rg*8+7 (rg = tid>>4)
    const int k2 = tid & 15;
    const int rg = tid >> 4;
    int papd8[8];
    if (EPI == 0) {
        #pragma unroll
        for (int r = 0; r < 8; r++) {
            int row = rg * 8 + r;
            int ap2 = pix0 + row;
            int apc2 = ap2 < NPIX ? ap2 : NPIX - 1;
            int ay = apc2 / SP, ax = apc2 - ay * SP;
            papd8[r] = (ay + 1) * PW + ax + 1;
        }
    }
    // EPI1 (old style): thread owns one row, all 32 k
    const int arow = tid & 127;
    const int ap = pix0 + arow;
    const int apc = ap < NPIX ? ap : NPIX - 1;
    const int apy = apc / SP;
    const int apx = apc - apy * SP;
    const int papd = (apy + 1) * PW + apx + 1;

    uint32_t ar[(EPI == 0) ? 16 : AE];

    auto ldgA = [&](int s) {
        if (EPI == 0) {
            int4 tt = *(const int4*)(tapS + (s << 5) + 2 * k2);
            const uint32_t* b0 = (tt.y ? in1i : in0i) + tt.x;
            const uint32_t* b1 = (tt.w ? in1i : in0i) + tt.z;
            #pragma unroll
            for (int r = 0; r < 8; r++) {
                ar[r] = __ldg(b0 + papd8[r]);
                ar[8 + r] = __ldg(b1 + papd8[r]);
            }
        } else {
            const int k0 = s << 5;
            #pragma unroll
            for (int e = 0; e < AE; e++) {
                int2 t = tapS[k0 + e];
                const uint32_t* base = t.y ? in1i : in0i;
                ar[e] = __ldg(base + t.x + papd);
            }
        }
    };
    auto stsA = [&](int s) {
        if (EPI == 0) {
            char* bb = smem + (s & 1) * BUF + rg * 512;
            #pragma unroll
            for (int rp = 0; rp < 4; rp++) {
                char* b2 = bb + ((k2 * 4) ^ (rp << 4));
                #pragma unroll
                for (int q = 0; q < 2; q++) {
                    int r = rp * 2 + q;
                    uint32_t hi, lo;
                    asm("prmt.b32 %0, %1, %2, 0x7632;" : "=r"(hi) : "r"(ar[r]), "r"(ar[8 + r]));
                    asm("prmt.b32 %0, %1, %2, 0x5410;" : "=r"(lo) : "r"(ar[r]), "r"(ar[8 + r]));
                    *(uint32_t*)(b2 + r * 64) = hi;
                    *(uint32_t*)(b2 + r * 64 + APLANE) = lo;
                }
            }
        } else {
            char* buf = smem + (s & 1) * BUF;
            #pragma unroll
            for (int e = 0; e < AE; e += 2) {
                int off = swz(arow, e * 2);
                uint32_t hi2 = (ar[e] >> 16) | (ar[e + 1] & 0xffff0000u);
                uint32_t lo2 = (ar[e] & 0xffffu) | (ar[e + 1] << 16);
                *(uint32_t*)(buf + off) = hi2;
                *(uint32_t*)(buf + APLANE + off) = lo2;
            }
        }
    };
    auto cpB = [&](int s) {
        const uint32_t bb = sb + (s & 1) * BUF + 2 * APLANE;
        const int k0 = s << 5;
        const __nv_bfloat16* wh = Whi + k0;
        const __nv_bfloat16* wl = Wlo + k0;
        #pragma unroll
        for (int i = 0; i < NCH * 4 / NTH; i++) {
            int idx = tid + i * NTH;
            int n = idx >> 2, j = idx & 3;
            long wr = (long)(nbase + n) * Kpad + j * 8;
            int off = swz(n, j * 16);
            cp_async16(bb + off, wh + wr);
            cp_async16(bb + BPLANE + off, wl + wr);
        }
        CP_COMMIT();
    };

    float acc[4][4][4];
    #pragma unroll
    for (int a = 0; a < 4; a++)
        #pragma unroll
        for (int b = 0; b < 4; b++)
            #pragma unroll
            for (int c = 0; c < 4; c++) acc[a][b][c] = 0.f;

    // ---- prologue ----
    for (int i = tid; i < Kpad; i += NTH) tapS[i] = tap[i];
    cpB(0);
    if (EPI == 0) {
        #pragma unroll
        for (int i = 0; i < 1024 / NTH; i++) {
            int idx4 = tid + i * NTH;
            int p = idx4 >> 3, jq = idx4 & 7;
            int pg = pix0 + p;
            float4 v = make_float4(0.f, 0.f, 0.f, 0.f);
            if (pg < NPIX)
                v = *(const float4*)(out_c + ((long)img * NPIX + pg) * 64 + nblk * 32 + jq * 4);
            *(float4*)(cs + p * 36 + jq * 4) = v;
        }
    }
    __syncthreads();          // taps visible
    ldgA(0);
    stsA(0);
    ldgA(1);
    CP_WAIT(0);
    __syncthreads();

    for (int s = 0; s < nstage; s++) {
        if (s + 1 < nstage) cpB(s + 1);   // buffer released at prev barrier

        const uint32_t cur = sb + (s & 1) * BUF;
        const uint32_t sAh = cur, sAl = cur + APLANE;
        const uint32_t sBh = cur + 2 * APLANE, sBl = sBh + BPLANE;

        #pragma unroll
        for (int h = 0; h < 2; h++) {
            uint32_t bh[2][4], bl[2][4];
            const int brow = wn * 32 + ((l >> 4) & 1) * 8 + (l & 7);
            const int bko = (h * 16 + ((l >> 3) & 1) * 8) * 2;
            #pragma unroll
            for (int nf2 = 0; nf2 < 2; nf2++) {
                LDSM4(bh[nf2], sBh + swz(brow + nf2 * 16, bko));
                LDSM4(bl[nf2], sBl + swz(brow + nf2 * 16, bko));
            }
            const int aro = wm * 64 + (l & 15);
            const int ako = (h * 16 + (l >> 4) * 8) * 2;
            #pragma unroll
            for (int mf = 0; mf < 4; mf++) {
                uint32_t ah[4], al[4];
                LDSM4(ah, sAh + swz(aro + mf * 16, ako));
                LDSM4(al, sAl + swz(aro + mf * 16, ako));
                #pragma unroll
                for (int nf = 0; nf < 4; nf++) {
                    const uint32_t* bhp = &bh[nf >> 1][(nf & 1) * 2];
                    const uint32_t* blp = &bl[nf >> 1][(nf & 1) * 2];
                    mma_bf16(acc[mf][nf], ah, bhp);
                    mma_bf16(acc[mf][nf], ah, blp);
                    mma_bf16(acc[mf][nf], al, bhp);
                }
            }
        }
        if (s + 1 < nstage) stsA(s + 1);
        if (s + 2 < nstage) ldgA(s + 2);
        CP_WAIT(0);
        __syncthreads();
    }

    if (EPI == 0) {
        #pragma unroll
        for (int mf = 0; mf < 4; mf++) {
            #pragma unroll
            for (int c = 0; c < 4; c++) {
                int p = wm * 64 + mf * 16 + (l >> 2) + ((c >> 1) & 1) * 8;
                int j = wn * 8 + (l & 3) * 2 + (c & 1);
                int u = nblk * 32 + j;
                float zi = acc[mf][0][c] + __ldg(bias + u);
                float zf = acc[mf][1][c] + __ldg(bias + 64 + u);
                float zo = acc[mf][2][c] + __ldg(bias + 128 + u);
                float zg = acc[mf][3][c] + __ldg(bias + 192 + u);
                if (pix0 + p < NPIX) {
                    float ig = sigm(zi), fg = sigm(zf), og = sigm(zo);
                    float gg = tanh_acc(zg);
                    float cn = fg * cs[p * 36 + j] + ig * gg;
                    cs[p * 36 + j] = cn;
                    hs[p * 33 + j] = pack_hl(og * tanh_acc(cn));
                }
            }
        }
        __syncthreads();
        uint32_t* out_h = (uint32_t*)out_h_;
        #pragma unroll
        for (int i = 0; i < 1024 / NTH; i++) {
            int idx4 = tid + i * NTH;
            int p = idx4 >> 3, jq = idx4 & 7;
            int pg = pix0 + p;
            if (pg < NPIX)
                *(float4*)(out_c + ((long)img * NPIX + pg) * 64 + nblk * 32 + jq * 4) =
                    *(const float4*)(cs + p * 36 + jq * 4);
        }
        #pragma unroll
        for (int uu = 0; uu < 32 * 32 / NTH; uu++) {   // 32 units / CTA
            int unit = wid + (NTH / 32) * uu;
            #pragma unroll
            for (int i = 0; i < 4; i++) {
                int px = i * 32 + l;
                int pg = pix0 + px;
                if (pg < NPIX) {
                    int gy = pg / SP, gx = pg - gy * SP;
                    out_h[((long)img * (HID + 1) + nblk * 32 + unit) * PPLANE
                          + (gy + 1) * PW + gx + 1] = hs[px * 33 + unit];
                }
            }
        }
    } else {
        float* out_h = (float*)out_h_;
        #pragma unroll
        for (int mf = 0; mf < 4; mf++) {
            #pragma unroll
            for (int c = 0; c < 4; c++) {
                int p = pix0 + wm * 64 + mf * 16 + (l >> 2) + ((c >> 1) & 1) * 8;
                #pragma unroll
                for (int nf = 0; nf < 4; nf++) {
                    int n = wn * 32 + nf * 8 + (l & 3) * 2 + (c & 1);
                    float v = acc[mf][nf][c] + __ldg(bias + n);
                    if (p < NPIX)
                        out_h[((long)img * HID + n) * NPIX + p] = fmaxf(v, 0.f);
                }
            }
        }
    }
}

// ---------------- maxpool 2x2 stride 2 ----------------
__global__ void pool_kernel(const float* __restrict__ y, float* __restrict__ out) {
    int idx = blockIdx.x * blockDim.x + threadIdx.x;
    if (idx >= BATCH * HID * POOLD * POOLD) return;
    int j = idx % POOLD;
    int i = (idx / POOLD) % POOLD;
    int ch = (idx / (POOLD * POOLD)) % HID;
    int b = idx / (POOLD * POOLD * HID);
    const float* p = y + ((long)(b * HID + ch)) * NPIX + (2 * i) * SP + 2 * j;
    float m = fmaxf(fmaxf(p[0], p[1]), fmaxf(p[SP], p[SP + 1]));
    out[(long)b * FEAT + ch * (POOLD * POOLD) + i * POOLD + j] = m;
}

// ---------------- FC: one warp per output element ----------------
__global__ void fc_kernel(const float* __restrict__ in, const float* __restrict__ w,
                          const float* __restrict__ b, float* __restrict__ out,
                          int M, int N, int K, int relu) {
    int warp = (blockIdx.x * blockDim.x + threadIdx.x) >> 5;
    int lane = threadIdx.x & 31;
    if (warp >= M * N) return;
    int m = warp / N, n = warp - m * N;
    const float* ir = in + (long)m * K;
    const float* wr = w + (long)n * K;
    float s = 0.f;
    for (int k = lane; k < K; k += 32) s += ir[k] * wr[k];
    #pragma unroll
    for (int o = 16; o; o >>= 1) s += __shfl_xor_sync(0xFFFFFFFFu, s, o);
    if (lane == 0) {
        s += b[n];
        if (relu) s = fmaxf(s, 0.f);
        out[(long)m * N + n] = s;
    }
}

__global__ void lsm_kernel(const float* __restrict__ in, float* __restrict__ out) {
    int m = blockIdx.x * blockDim.x + threadIdx.x;
    if (m >= BATCH) return;
    float a = in[2 * m], b = in[2 * m + 1];
    float mx = fmaxf(a, b);
    float l = mx + logf(expf(a - mx) + expf(b - mx));
    out[2 * m] = a - l;
    out[2 * m + 1] = b - l;
}

// ---------------- launch ----------------
extern "C" void kernel_launch(void* const* d_in, const int* in_sizes, int n_in,
                              void* d_out, int out_size) {
    const float* x   = (const float*)d_in[0];
    const float* lg  = (const float*)d_in[1];
    const float* lb  = (const float*)d_in[2];
    const float* w0  = (const float*)d_in[3];
    const float* b0  = (const float*)d_in[4];
    const float* w1  = (const float*)d_in[5];
    const float* b1  = (const float*)d_in[6];
    const float* wc  = (const float*)d_in[7];
    const float* bc  = (const float*)d_in[8];
    const float* wf1 = (const float*)d_in[9];
    const float* bf1 = (const float*)d_in[10];
    const float* wf2 = (const float*)d_in[11];
    const float* bf2 = (const float*)d_in[12];
    const float* wf3 = (const float*)d_in[13];
    const float* bf3 = (const float*)d_in[14];
    float* out = (float*)d_out;

    uint32_t *xn, *h0a, *h0b, *h1a, *h1b;
    float *c0, *c1, *y, *pool, *f1, *f2, *f3;
    __nv_bfloat16 *w0h, *w0l, *w1h, *w1l, *wch, *wcl;
    int2 *tap0, *tap1, *tapc;
    cudaGetSymbolAddress((void**)&xn,  g_xn);
    cudaGetSymbolAddress((void**)&h0a, g_h0a);
    cudaGetSymbolAddress((void**)&h0b, g_h0b);
    cudaGetSymbolAddress((void**)&h1a, g_h1a);
    cudaGetSymbolAddress((void**)&h1b, g_h1b);
    cudaGetSymbolAddress((void**)&c0,  g_c0);
    cudaGetSymbolAddress((void**)&c1,  g_c1);
    cudaGetSymbolAddress((void**)&y,   g_y);
    cudaGetSymbolAddress((void**)&pool, g_pool);
    cudaGetSymbolAddress((void**)&f1, g_f1);
    cudaGetSymbolAddress((void**)&f2, g_f2);
    cudaGetSymbolAddress((void**)&f3, g_f3);
    cudaGetSymbolAddress((void**)&w0h, g_w0h);
    cudaGetSymbolAddress((void**)&w0l, g_w0l);
    cudaGetSymbolAddress((void**)&w1h, g_w1h);
    cudaGetSymbolAddress((void**)&w1l, g_w1l);
    cudaGetSymbolAddress((void**)&wch, g_wch);
    cudaGetSymbolAddress((void**)&wcl, g_wcl);
    cudaGetSymbolAddress((void**)&tap0, g_tap0);
    cudaGetSymbolAddress((void**)&tap1, g_tap1);
    cudaGetSymbolAddress((void**)&tapc, g_tapc);

    const int SMEM0 = 2 * 32768 + TAPSZ + 128 * 36 * 4 + 128 * 33 * 4;  // 110080
    const int SMEM1 = 2 * 24576 + TAPSZ + 128 * 36 * 4 + 128 * 33 * 4;  // 93696
    cudaFuncSetAttribute(convmma_kernel<4, 0>, cudaFuncAttributeMaxDynamicSharedMemorySize, SMEM0);
    cudaFuncSetAttribute(convmma_kernel<2, 1>, cudaFuncAttributeMaxDynamicSharedMemorySize, SMEM1);

    zero_all_kernel<<<(int)((NXZ + 255) / 256), 256>>>(xn, h0a, h0b, h1a, h1b, c0, c1);

    const int nln = BATCH * TSTEPS * NPIX;
    ln_kernel<<<(nln + 255) / 256, 256>>>(x, lg, lb, xn);

    const int nprep = GATES * K0PAD + GATES * K1PAD + HID * KCPAD + K0PAD + K1PAD + KCPAD;
    prep_kernel<<<(nprep + 255) / 256, 256>>>(w0, w1, wc);

    uint32_t* h0buf[2] = {h0a, h0b};
    uint32_t* h1buf[2] = {h1a, h1b};
    dim3 grid0(5, BATCH, 2);
    for (int t = 0; t < TSTEPS; t++) {
        int r = t & 1;
        const uint32_t* xt = xn + (long)t * BATCH * (CIN + 1) * PPLANE;
        convmma_kernel<4, 0><<<grid0, 256, SMEM0>>>(
            xt, CIN, h0buf[r], HID, tap0, w0h, w0l, K0PAD, b0, h0buf[1 - r], c0);
        convmma_kernel<4, 0><<<grid0, 256, SMEM0>>>(
            h0buf[1 - r], HID, h1buf[r], HID, tap1, w1h, w1l, K1PAD, b1, h1buf[1 - r], c1);
    }
    const uint32_t* hfin = h1buf[0];   // t=19 (r=1) wrote h1buf[0]

    dim3 grid1(5, BATCH, 1);
    convmma_kernel<2, 1><<<grid1, 128, SMEM1>>>(
        hfin, HID, hfin, HID, tapc, wch, wcl, KCPAD, bc, y, (float*)0);

    const int npool = BATCH * HID * POOLD * POOLD;
    pool_kernel<<<(npool + 255) / 256, 256>>>(y, pool);
    {
        int warps = BATCH * FC1N;
        fc_kernel<<<(warps * 32 + 255) / 256, 256>>>(pool, wf1, bf1, f1, BATCH, FC1N, FEAT, 1);
    }
    {
        int warps = BATCH * FC2N;
        fc_kernel<<<(warps * 32 + 255) / 256, 256>>>(f1, wf2, bf2, f2, BATCH, FC2N, FC1N, 1);
    }
    {
        int warps = BATCH * 2;
        fc_kernel<<<(warps * 32 + 255) / 256, 256>>>(f2, wf3, bf3, f3, BATCH, 2, FC2N, 0);
    }
    lsm_kernel<<<1, BATCH>>>(f3, out);
}

// round 14
// speedup vs baseline: 2.1337x; 1.1847x over previous
#include <cuda_runtime.h>
#include <cuda_bf16.h>
#include <math.h>
#include <cstdint>

// ---------------- problem constants ----------------
#define BATCH 64
#define TSTEPS 20
#define CIN 25
#define HID 64
#define SP 25
#define NPIX 625
#define GATES 256
#define POOLD 12
#define FEAT 9216
#define FC1N 128
#define FC2N 64

#define PW 27
#define PPLANE 729

#define K0TOT ((CIN + HID) * 9)   // 801
#define K0PAD 832
#define K1TOT (2 * HID * 9)       // 1152
#define K1PAD 1152
#define KCTOT (HID * 9)           // 576
#define KCPAD 576
#define TAPSZ 9216                // 1152 * sizeof(int2)

// ---------------- scratch (device globals, no allocation) ----------------
__device__ __align__(16) uint32_t g_xn[(long)TSTEPS * BATCH * (CIN + 1) * PPLANE];
__device__ __align__(16) uint32_t g_h0a[(long)BATCH * (HID + 1) * PPLANE];
__device__ __align__(16) uint32_t g_h0b[(long)BATCH * (HID + 1) * PPLANE];
__device__ __align__(16) uint32_t g_h1a[(long)BATCH * (HID + 1) * PPLANE];
__device__ __align__(16) uint32_t g_h1b[(long)BATCH * (HID + 1) * PPLANE];
__device__ __align__(16) float g_c0[(long)BATCH * NPIX * HID];
__device__ __align__(16) float g_c1[(long)BATCH * NPIX * HID];
__device__ __align__(16) float g_y [(long)BATCH * HID * NPIX];
__device__ __align__(16) float g_pool[(long)BATCH * FEAT];
__device__ float g_f1[BATCH * FC1N];
__device__ float g_f2[BATCH * FC2N];
__device__ float g_f3[BATCH * 2];
__device__ __align__(16) __nv_bfloat16 g_w0h[GATES * K0PAD];
__device__ __align__(16) __nv_bfloat16 g_w0l[GATES * K0PAD];
__device__ __align__(16) __nv_bfloat16 g_w1h[GATES * K1PAD];
__device__ __align__(16) __nv_bfloat16 g_w1l[GATES * K1PAD];
__device__ __align__(16) __nv_bfloat16 g_wch[HID * KCPAD];
__device__ __align__(16) __nv_bfloat16 g_wcl[HID * KCPAD];
__device__ __align__(16) int2 g_tap0[K0PAD];
__device__ __align__(16) int2 g_tap1[K1PAD];
__device__ __align__(16) int2 g_tapc[KCPAD];

// ---------------- conv argument sets (for fused dual-layer launches) ----------------
struct ConvSet {
    const uint32_t* in0;
    const uint32_t* in1;
    int C0, C1;
    const int2* tap;
    const __nv_bfloat16* Whi;
    const __nv_bfloat16* Wlo;
    int Kpad;
    const float* bias;
    void* out_h;
    float* out_c;
};
struct ConvArgs { ConvSet s[2]; };

// ---------------- helpers ----------------
__device__ __forceinline__ uint32_t smem_u32(const void* p) {
    uint32_t a;
    asm("{ .reg .u64 t; cvta.to.shared.u64 t, %1; cvt.u32.u64 %0, t; }" : "=r"(a) : "l"(p));
    return a;
}
#define LDSM4(r, a) \
    asm volatile("ldmatrix.sync.aligned.m8n8.x4.shared.b16 {%0,%1,%2,%3}, [%4];" \
        : "=r"((r)[0]), "=r"((r)[1]), "=r"((r)[2]), "=r"((r)[3]) : "r"(a))

__device__ __forceinline__ void mma_bf16(float* c, const uint32_t* a, const uint32_t* b) {
    asm volatile(
        "mma.sync.aligned.m16n8k16.row.col.f32.bf16.bf16.f32 "
        "{%0,%1,%2,%3}, {%4,%5,%6,%7}, {%8,%9}, {%0,%1,%2,%3};"
        : "+f"(c[0]), "+f"(c[1]), "+f"(c[2]), "+f"(c[3])
        : "r"(a[0]), "r"(a[1]), "r"(a[2]), "r"(a[3]), "r"(b[0]), "r"(b[1]));
}
__device__ __forceinline__ void cp_async16(uint32_t dst, const void* src) {
    asm volatile("cp.async.cg.shared.global [%0], [%1], 16;" :: "r"(dst), "l"(src));
}
#define CP_COMMIT() asm volatile("cp.async.commit_group;" ::: "memory")
#define CP_WAIT(n)  asm volatile("cp.async.wait_group %0;" :: "n"(n) : "memory")

__device__ __forceinline__ float sigm(float x) { return 1.f / (1.f + __expf(-x)); }
__device__ __forceinline__ float tanh_acc(float x) {
    float e = __expf(-2.f * fabsf(x));
    float t = (1.f - e) / (1.f + e);
    return copysignf(t, x);
}
__device__ __forceinline__ uint32_t pack_hl(float v) {
    __nv_bfloat16 h = __float2bfloat16(v);
    float hf = __bfloat162float(h);
    __nv_bfloat16 lo = __float2bfloat16(v - hf);
    return ((uint32_t)__bfloat16_as_ushort(h) << 16) | (uint32_t)__bfloat16_as_ushort(lo);
}
__device__ __forceinline__ int swz(int row, int kbyte) {
    return row * 64 + (kbyte ^ (((row >> 1) & 3) << 4));
}

// ---------------- zero all recurrent/padded state ----------------
#define NXZ ((long)TSTEPS * BATCH * (CIN + 1) * PPLANE)
#define NHZ ((long)BATCH * (HID + 1) * PPLANE)
#define NCZ ((long)BATCH * NPIX * HID)
__global__ void zero_all_kernel(uint32_t* xn, uint32_t* h0a, uint32_t* h0b,
                                uint32_t* h1a, uint32_t* h1b, float* c0, float* c1) {
    long i = (long)blockIdx.x * blockDim.x + threadIdx.x;
    if (i < NXZ) xn[i] = 0u;
    if (i < NHZ) { h0a[i] = 0u; h0b[i] = 0u; h1a[i] = 0u; h1b[i] = 0u; }
    if (i < NCZ) { c0[i] = 0.f; c1[i] = 0.f; }
}

// ---------------- LayerNorm -> padded planes ----------------
__global__ void ln_kernel(const float* __restrict__ x,
                          const float* __restrict__ gamma,
                          const float* __restrict__ beta,
                          uint32_t* __restrict__ xn) {
    int idx = blockIdx.x * blockDim.x + threadIdx.x;
    if (idx >= BATCH * TSTEPS * NPIX) return;
    int p = idx % NPIX;
    int t = (idx / NPIX) % TSTEPS;
    int b = idx / (NPIX * TSTEPS);
    const float* base = x + ((long)(b * TSTEPS + t) * CIN) * NPIX + p;
    float v[CIN];
    float s = 0.f;
    #pragma unroll
    for (int c = 0; c < CIN; c++) { v[c] = base[c * NPIX]; s += v[c]; }
    float mu = s * (1.f / CIN);
    float q = 0.f;
    #pragma unroll
    for (int c = 0; c < CIN; c++) { float d = v[c] - mu; q += d * d; }
    float rs = rsqrtf(q * (1.f / CIN) + 1e-5f);
    int py = p / SP, px = p - py * SP;
    uint32_t* ob = xn + ((long)(t * BATCH + b) * (CIN + 1)) * PPLANE
                      + (py + 1) * PW + px + 1;
    #pragma unroll
    for (int c = 0; c < CIN; c++) ob[c * PPLANE] = pack_hl((v[c] - mu) * rs * gamma[c] + beta[c]);
}

// ---------------- merged prep: weight hi/lo conversion + tap tables ----------------
__device__ __forceinline__ void wconv(const float* W, __nv_bfloat16* hi, __nv_bfloat16* lo,
                                      int i, int Ktot, int Kpad, int perm) {
    int o = i / Kpad, k = i - o * Kpad;
    int orig = perm ? (((o >> 3) & 3) * 64 + ((o >> 7) & 1) * 32 + ((o >> 5) & 3) * 8 + (o & 7)) : o;
    float v = (k < Ktot) ? W[(long)orig * Ktot + k] : 0.f;
    __nv_bfloat16 h = __float2bfloat16(v);
    hi[i] = h;
    lo[i] = __float2bfloat16(v - __bfloat162float(h));
}
__device__ __forceinline__ int2 tap_make(int j, int Ktot, int C0) {
    if (j >= Ktot) return make_int2(C0 * PPLANE, 0);
    int cc = j / 9, r = j - cc * 9;
    int ky = r / 3 - 1, kx = r - (r / 3) * 3 - 1;
    int sel = cc >= C0;
    int c = sel ? cc - C0 : cc;
    return make_int2(c * PPLANE + ky * PW + kx, sel);
}
__global__ void prep_kernel(const float* w0, const float* w1, const float* wc) {
    const int S0 = GATES * K0PAD, S1 = GATES * K1PAD, S2 = HID * KCPAD;
    int i = blockIdx.x * blockDim.x + threadIdx.x;
    if (i < S0) { wconv(w0, g_w0h, g_w0l, i, K0TOT, K0PAD, 1); return; }
    i -= S0;
    if (i < S1) { wconv(w1, g_w1h, g_w1l, i, K1TOT, K1PAD, 1); return; }
    i -= S1;
    if (i < S2) { wconv(wc, g_wch, g_wcl, i, KCTOT, KCPAD, 0); return; }
    i -= S2;
    if (i < K0PAD) { g_tap0[i] = tap_make(i, K0TOT, CIN); return; }
    i -= K0PAD;
    if (i < K1PAD) { g_tap1[i] = tap_make(i, K1TOT, HID); return; }
    i -= K1PAD;
    if (i < KCPAD) { g_tapc[i] = tap_make(i, KCTOT, HID); return; }
}

// ---------------- pipelined mma.sync implicit-GEMM conv (+fused epilogue) ----------------
// blockIdx.z decode: si = z>>1 (which ConvSet), nblk = z&1 (N-block of 128 ch).
// CTA: M=128 pixels x 128 ch; 8 warps (2 M) x (4 N); warp tile 64x32.
// EPI=0: fused LSTM gates (2 CTAs/SM). EPI=1: bias+relu, NWN=2 (single launch).
template<int NWN, int EPI>
__global__ __launch_bounds__(NWN * 64, 2)
void convmma_kernel(ConvArgs args) {
    constexpr int NTH = NWN * 64;
    constexpr int NCH = NWN * 32;
    constexpr int APLANE = 128 * 64;
    constexpr int BPLANE = NCH * 64;
    constexpr int BUF = 2 * APLANE + 2 * BPLANE;
    constexpr int AE = 4096 / NTH;

    extern __shared__ char smem[];
    const uint32_t sb = smem_u32(smem);
    int2* tapS = (int2*)(smem + 2 * BUF);
    float* cs = (float*)(smem + 2 * BUF + TAPSZ);                       // [128][36]
    uint32_t* hs = (uint32_t*)(smem + 2 * BUF + TAPSZ + 128 * 36 * 4);  // [128][33]

    const int si = (EPI == 0) ? (blockIdx.z >> 1) : 0;
    const ConvSet& S = args.s[si];
    const int nblk = (EPI == 0) ? (blockIdx.z & 1) : 0;
    const int nbase = nblk * NCH;
    const int C0 = S.C0, C1 = S.C1;
    const int Kpad = S.Kpad;
    const int2* __restrict__ tap = S.tap;
    const __nv_bfloat16* __restrict__ Whi = S.Whi;
    const __nv_bfloat16* __restrict__ Wlo = S.Wlo;
    const float* __restrict__ bias = S.bias;
    float* __restrict__ out_c = S.out_c;

    const int tid = threadIdx.x;
    const int l = tid & 31;
    const int wid = tid >> 5;
    const int wm = wid & 1;
    const int wn = wid >> 1;
    const int img = blockIdx.y;
    const int pix0 = blockIdx.x * 128;

    const int arow = tid & 127;
    const int ap = pix0 + arow;
    const int apc = ap < NPIX ? ap : NPIX - 1;
    const int apy = apc / SP;
    const int apx = apc - apy * SP;
    const int papd = (apy + 1) * PW + apx + 1;
    const int kbase = tid >> 7;

    const uint32_t* in0i = S.in0 + (long)img * (C0 + 1) * PPLANE;
    const uint32_t* in1i = S.in1 + (long)img * (C1 + 1) * PPLANE;

    const int nstage = Kpad >> 5;

    uint32_t ar[AE];

    auto ldgA = [&](int s) {
        const int k0 = s << 5;
        #pragma unroll
        for (int e = 0; e < AE; e++) {
            int k = kbase * AE + e;
            int2 t = tapS[k0 + k];
            const uint32_t* base = t.y ? in1i : in0i;
            ar[e] = __ldg(base + t.x + papd);
        }
    };
    auto stsA = [&](int s) {
        char* buf = smem + (s & 1) * BUF;
        #pragma unroll
        for (int e = 0; e < AE; e += 2) {
            int k = kbase * AE + e;
            int off = swz(arow, k * 2);
            uint32_t hi2 = (ar[e] >> 16) | (ar[e + 1] & 0xffff0000u);
            uint32_t lo2 = (ar[e] & 0xffffu) | (ar[e + 1] << 16);
            *(uint32_t*)(buf + off) = hi2;
            *(uint32_t*)(buf + APLANE + off) = lo2;
        }
    };
    auto cpB = [&](int s) {
        const uint32_t bb = sb + (s & 1) * BUF + 2 * APLANE;
        const int k0 = s << 5;
        const __nv_bfloat16* wh = Whi + k0;
        const __nv_bfloat16* wl = Wlo + k0;
        #pragma unroll
        for (int i = 0; i < NCH * 4 / NTH; i++) {
            int idx = tid + i * NTH;
            int n = idx >> 2, j = idx & 3;
            long wr = (long)(nbase + n) * Kpad + j * 8;
            int off = swz(n, j * 16);
            cp_async16(bb + off, wh + wr);
            cp_async16(bb + BPLANE + off, wl + wr);
        }
        CP_COMMIT();
    };

    float acc[4][4][4];
    #pragma unroll
    for (int a = 0; a < 4; a++)
        #pragma unroll
        for (int b = 0; b < 4; b++)
            #pragma unroll
            for (int c = 0; c < 4; c++) acc[a][b][c] = 0.f;

    // ---- prologue ----
    for (int i = tid; i < Kpad; i += NTH) tapS[i] = tap[i];
    cpB(0);
    if (EPI == 0) {
        #pragma unroll
        for (int i = 0; i < 1024 / NTH; i++) {
            int idx4 = tid + i * NTH;
            int p = idx4 >> 3, jq = idx4 & 7;
            int pg = pix0 + p;
            float4 v = make_float4(0.f, 0.f, 0.f, 0.f);
            if (pg < NPIX)
                v = *(const float4*)(out_c + ((long)img * NPIX + pg) * 64 + nblk * 32 + jq * 4);
            *(float4*)(cs + p * 36 + jq * 4) = v;
        }
    }
    __syncthreads();
    ldgA(0);
    stsA(0);
    ldgA(1);
    CP_WAIT(0);
    __syncthreads();

    for (int s = 0; s < nstage; s++) {
        if (s + 1 < nstage) cpB(s + 1);

        const uint32_t cur = sb + (s & 1) * BUF;
        const uint32_t sAh = cur, sAl = cur + APLANE;
        const uint32_t sBh = cur + 2 * APLANE, sBl = sBh + BPLANE;

        #pragma unroll
        for (int h = 0; h < 2; h++) {
            uint32_t bh[2][4], bl[2][4];
            const int brow = wn * 32 + ((l >> 4) & 1) * 8 + (l & 7);
            const int bko = (h * 16 + ((l >> 3) & 1) * 8) * 2;
            #pragma unroll
            for (int nf2 = 0; nf2 < 2; nf2++) {
                LDSM4(bh[nf2], sBh + swz(brow + nf2 * 16, bko));
                LDSM4(bl[nf2], sBl + swz(brow + nf2 * 16, bko));
            }
            const int aro = wm * 64 + (l & 15);
            const int ako = (h * 16 + (l >> 4) * 8) * 2;
            #pragma unroll
            for (int mf = 0; mf < 4; mf++) {
                uint32_t ah[4], al[4];
                LDSM4(ah, sAh + swz(aro + mf * 16, ako));
                LDSM4(al, sAl + swz(aro + mf * 16, ako));
                #pragma unroll
                for (int nf = 0; nf < 4; nf++) {
                    const uint32_t* bhp = &bh[nf >> 1][(nf & 1) * 2];
                    const uint32_t* blp = &bl[nf >> 1][(nf & 1) * 2];
                    mma_bf16(acc[mf][nf], ah, bhp);
                    mma_bf16(acc[mf][nf], ah, blp);
                    mma_bf16(acc[mf][nf], al, bhp);
                }
            }
        }
        if (s + 1 < nstage) stsA(s + 1);
        if (s + 2 < nstage) ldgA(s + 2);
        CP_WAIT(0);
        __syncthreads();
    }

    if (EPI == 0) {
        #pragma unroll
        for (int mf = 0; mf < 4; mf++) {
            #pragma unroll
            for (int c = 0; c < 4; c++) {
                int p = wm * 64 + mf * 16 + (l >> 2) + ((c >> 1) & 1) * 8;
                int j = wn * 8 + (l & 3) * 2 + (c & 1);
                int u = nblk * 32 + j;
                float zi = acc[mf][0][c] + __ldg(bias + u);
                float zf = acc[mf][1][c] + __ldg(bias + 64 + u);
                float zo = acc[mf][2][c] + __ldg(bias + 128 + u);
                float zg = acc[mf][3][c] + __ldg(bias + 192 + u);
                if (pix0 + p < NPIX) {
                    float ig = sigm(zi), fg = sigm(zf), og = sigm(zo);
                    float gg = tanh_acc(zg);
                    float cn = fg * cs[p * 36 + j] + ig * gg;
                    cs[p * 36 + j] = cn;
                    hs[p * 33 + j] = pack_hl(og * tanh_acc(cn));
                }
            }
        }
        __syncthreads();
        uint32_t* out_h = (uint32_t*)S.out_h;
        #pragma unroll
        for (int i = 0; i < 1024 / NTH; i++) {
            int idx4 = tid + i * NTH;
            int p = idx4 >> 3, jq = idx4 & 7;
            int pg = pix0 + p;
            if (pg < NPIX)
                *(float4*)(out_c + ((long)img * NPIX + pg) * 64 + nblk * 32 + jq * 4) =
                    *(const float4*)(cs + p * 36 + jq * 4);
        }
        #pragma unroll
        for (int uu = 0; uu < 32 * 32 / NTH; uu++) {
            int unit = wid + (NTH / 32) * uu;
            #pragma unroll
            for (int i = 0; i < 4; i++) {
                int px = i * 32 + l;
                int pg = pix0 + px;
                if (pg < NPIX) {
                    int gy = pg / SP, gx = pg - gy * SP;
                    out_h[((long)img * (HID + 1) + nblk * 32 + unit) * PPLANE
                          + (gy + 1) * PW + gx + 1] = hs[px * 33 + unit];
                }
            }
        }
    } else {
        float* out_h = (float*)S.out_h;
        #pragma unroll
        for (int mf = 0; mf < 4; mf++) {
            #pragma unroll
            for (int c = 0; c < 4; c++) {
                int p = pix0 + wm * 64 + mf * 16 + (l >> 2) + ((c >> 1) & 1) * 8;
                #pragma unroll
                for (int nf = 0; nf < 4; nf++) {
                    int n = wn * 32 + nf * 8 + (l & 3) * 2 + (c & 1);
                    float v = acc[mf][nf][c] + __ldg(bias + n);
                    if (p < NPIX)
                        out_h[((long)img * HID + n) * NPIX + p] = fmaxf(v, 0.f);
                }
            }
        }
    }
}

// ---------------- maxpool 2x2 stride 2 ----------------
__global__ void pool_kernel(const float* __restrict__ y, float* __restrict__ out) {
    int idx = blockIdx.x * blockDim.x + threadIdx.x;
    if (idx >= BATCH * HID * POOLD * POOLD) return;
    int j = idx % POOLD;
    int i = (idx / POOLD) % POOLD;
    int ch = (idx / (POOLD * POOLD)) % HID;
    int b = idx / (POOLD * POOLD * HID);
    const float* p = y + ((long)(b * HID + ch)) * NPIX + (2 * i) * SP + 2 * j;
    float m = fmaxf(fmaxf(p[0], p[1]), fmaxf(p[SP], p[SP + 1]));
    out[(long)b * FEAT + ch * (POOLD * POOLD) + i * POOLD + j] = m;
}

// ---------------- FC: one warp per output element ----------------
__global__ void fc_kernel(const float* __restrict__ in, const float* __restrict__ w,
                          const float* __restrict__ b, float* __restrict__ out,
                          int M, int N, int K, int relu) {
    int warp = (blockIdx.x * blockDim.x + threadIdx.x) >> 5;
    int lane = threadIdx.x & 31;
    if (warp >= M * N) return;
    int m = warp / N, n = warp - m * N;
    const float* ir = in + (long)m * K;
    const float* wr = w + (long)n * K;
    float s = 0.f;
    for (int k = lane; k < K; k += 32) s += ir[k] * wr[k];
    #pragma unroll
    for (int o = 16; o; o >>= 1) s += __shfl_xor_sync(0xFFFFFFFFu, s, o);
    if (lane == 0) {
        s += b[n];
        if (relu) s = fmaxf(s, 0.f);
        out[(long)m * N + n] = s;
    }
}

__global__ void lsm_kernel(const float* __restrict__ in, float* __restrict__ out) {
    int m = blockIdx.x * blockDim.x + threadIdx.x;
    if (m >= BATCH) return;
    float a = in[2 * m], b = in[2 * m + 1];
    float mx = fmaxf(a, b);
    float l = mx + logf(expf(a - mx) + expf(b - mx));
    out[2 * m] = a - l;
    out[2 * m + 1] = b - l;
}

// ---------------- launch ----------------
extern "C" void kernel_launch(void* const* d_in, const int* in_sizes, int n_in,
                              void* d_out, int out_size) {
    const float* x   = (const float*)d_in[0];
    const float* lg  = (const float*)d_in[1];
    const float* lb  = (const float*)d_in[2];
    const float* w0  = (const float*)d_in[3];
    const float* b0  = (const float*)d_in[4];
    const float* w1  = (const float*)d_in[5];
    const float* b1  = (const float*)d_in[6];
    const float* wc  = (const float*)d_in[7];
    const float* bc  = (const float*)d_in[8];
    const float* wf1 = (const float*)d_in[9];
    const float* bf1 = (const float*)d_in[10];
    const float* wf2 = (const float*)d_in[11];
    const float* bf2 = (const float*)d_in[12];
    const float* wf3 = (const float*)d_in[13];
    const float* bf3 = (const float*)d_in[14];
    float* out = (float*)d_out;

    uint32_t *xn, *h0a, *h0b, *h1a, *h1b;
    float *c0, *c1, *y, *pool, *f1, *f2, *f3;
    __nv_bfloat16 *w0h, *w0l, *w1h, *w1l, *wch, *wcl;
    int2 *tap0, *tap1, *tapc;
    cudaGetSymbolAddress((void**)&xn,  g_xn);
    cudaGetSymbolAddress((void**)&h0a, g_h0a);
    cudaGetSymbolAddress((void**)&h0b, g_h0b);
    cudaGetSymbolAddress((void**)&h1a, g_h1a);
    cudaGetSymbolAddress((void**)&h1b, g_h1b);
    cudaGetSymbolAddress((void**)&c0,  g_c0);
    cudaGetSymbolAddress((void**)&c1,  g_c1);
    cudaGetSymbolAddress((void**)&y,   g_y);
    cudaGetSymbolAddress((void**)&pool, g_pool);
    cudaGetSymbolAddress((void**)&f1, g_f1);
    cudaGetSymbolAddress((void**)&f2, g_f2);
    cudaGetSymbolAddress((void**)&f3, g_f3);
    cudaGetSymbolAddress((void**)&w0h, g_w0h);
    cudaGetSymbolAddress((void**)&w0l, g_w0l);
    cudaGetSymbolAddress((void**)&w1h, g_w1h);
    cudaGetSymbolAddress((void**)&w1l, g_w1l);
    cudaGetSymbolAddress((void**)&wch, g_wch);
    cudaGetSymbolAddress((void**)&wcl, g_wcl);
    cudaGetSymbolAddress((void**)&tap0, g_tap0);
    cudaGetSymbolAddress((void**)&tap1, g_tap1);
    cudaGetSymbolAddress((void**)&tapc, g_tapc);

    const int SMEM0 = 2 * 32768 + TAPSZ + 128 * 36 * 4 + 128 * 33 * 4;  // 110080
    const int SMEM1 = 2 * 24576 + TAPSZ + 128 * 36 * 4 + 128 * 33 * 4;  // 93696
    cudaFuncSetAttribute(convmma_kernel<4, 0>, cudaFuncAttributeMaxDynamicSharedMemorySize, SMEM0);
    cudaFuncSetAttribute(convmma_kernel<2, 1>, cudaFuncAttributeMaxDynamicSharedMemorySize, SMEM1);

    zero_all_kernel<<<(int)((NXZ + 255) / 256), 256>>>(xn, h0a, h0b, h1a, h1b, c0, c1);

    const int nln = BATCH * TSTEPS * NPIX;
    ln_kernel<<<(nln + 255) / 256, 256>>>(x, lg, lb, xn);

    const int nprep = GATES * K0PAD + GATES * K1PAD + HID * KCPAD + K0PAD + K1PAD + KCPAD;
    prep_kernel<<<(nprep + 255) / 256, 256>>>(w0, w1, wc);

    uint32_t* h0buf[2] = {h0a, h0b};
    uint32_t* h1buf[2] = {h1a, h1b};

    auto l0set = [&](int t) {   // layer0 at timestep t: reads h0buf[t&1], writes h0buf[1-(t&1)]
        ConvSet s;
        s.in0 = xn + (long)t * BATCH * (CIN + 1) * PPLANE;
        s.in1 = h0buf[t & 1];
        s.C0 = CIN; s.C1 = HID;
        s.tap = tap0; s.Whi = w0h; s.Wlo = w0l; s.Kpad = K0PAD;
        s.bias = b0; s.out_h = h0buf[1 - (t & 1)]; s.out_c = c0;
        return s;
    };
    auto l1set = [&](int t) {   // layer1 at timestep t: reads h0buf[1-(t&1)], h1buf[t&1]
        ConvSet s;
        s.in0 = h0buf[1 - (t & 1)];
        s.in1 = h1buf[t & 1];
        s.C0 = HID; s.C1 = HID;
        s.tap = tap1; s.Whi = w1h; s.Wlo = w1l; s.Kpad = K1PAD;
        s.bias = b1; s.out_h = h1buf[1 - (t & 1)]; s.out_c = c1;
        return s;
    };

    // L0(0) solo
    {
        ConvArgs a; a.s[0] = l0set(0); a.s[1] = a.s[0];
        convmma_kernel<4, 0><<<dim3(5, BATCH, 2), 256, SMEM0>>>(a);
    }
    // fused [L1(t) || L0(t+1)] for t = 0..18
    for (int t = 0; t < TSTEPS - 1; t++) {
        ConvArgs a; a.s[0] = l1set(t); a.s[1] = l0set(t + 1);
        convmma_kernel<4, 0><<<dim3(5, BATCH, 4), 256, SMEM0>>>(a);
    }
    // L1(19) solo
    {
        ConvArgs a; a.s[0] = l1set(TSTEPS - 1); a.s[1] = a.s[0];
        convmma_kernel<4, 0><<<dim3(5, BATCH, 2), 256, SMEM0>>>(a);
    }
    const uint32_t* hfin = h1buf[0];   // t=19 wrote h1buf[0]

    // conv1 + relu
    {
        ConvArgs a;
        ConvSet s;
        s.in0 = hfin; s.in1 = hfin;
        s.C0 = HID; s.C1 = HID;
        s.tap = tapc; s.Whi = wch; s.Wlo = wcl; s.Kpad = KCPAD;
        s.bias = bc; s.out_h = y; s.out_c = (float*)0;
        a.s[0] = s; a.s[1] = s;
        convmma_kernel<2, 1><<<dim3(5, BATCH, 1), 128, SMEM1>>>(a);
    }

    const int npool = BATCH * HID * POOLD * POOLD;
    pool_kernel<<<(npool + 255) / 256, 256>>>(y, pool);
    {
        int warps = BATCH * FC1N;
        fc_kernel<<<(warps * 32 + 255) / 256, 256>>>(pool, wf1, bf1, f1, BATCH, FC1N, FEAT, 1);
    }
    {
        int warps = BATCH * FC2N;
        fc_kernel<<<(warps * 32 + 255) / 256, 256>>>(f1, wf2, bf2, f2, BATCH, FC2N, FC1N, 1);
    }
    {
        int warps = BATCH * 2;
        fc_kernel<<<(warps * 32 + 255) / 256, 256>>>(f2, wf3, bf3, f3, BATCH, 2, FC2N, 0);
    }
    lsm_kernel<<<1, BATCH>>>(f3, out);
}